// round 1
// baseline (speedup 1.0000x reference)
#include <cuda_runtime.h>
#include <cuda_bf16.h>
#include <mma.h>

using namespace nvcuda;

#define BN 256      // batch
#define CN 65536    // classes
#define DN 2048     // feature dim
#define TM 128      // memory rows per block
#define KCH 32      // K chunk
#define NBLK (CN / TM)  // 512

// log2(e)/TEMP,  TEMP = 0.07
#define KSCALE 20.6099292786f
#define INV_TEMP (1.0f / 0.07f)

__device__ __align__(16) __nv_bfloat16 g_featB[BN * DN];  // bf16 features
__device__ float g_partial[NBLK * BN];                    // per-block masked sum-exp partials
__device__ float g_pos[BN];                               // fp32 positive logits

// exp(score) where score = dot / TEMP ; computed as 2^(dot * KSCALE).
// |dot| <= ~1 so exponent range is safe. Degree-5 poly, max rel err ~2.4e-6.
__device__ __forceinline__ float fast_expscore(float v) {
    float y = v * KSCALE;
    float n = rintf(y);
    float f = y - n;
    float p = 1.3333558e-3f;
    p = fmaf(p, f, 9.6181291e-3f);
    p = fmaf(p, f, 5.5504109e-2f);
    p = fmaf(p, f, 2.4022651e-1f);
    p = fmaf(p, f, 6.9314718e-1f);
    p = fmaf(p, f, 1.0f);
    return __int_as_float(__float_as_int(p) + (((int)n) << 23));
}

// ---------------------------------------------------------------------------
// Kernel 0: convert features fp32 -> bf16 once.
__global__ void prep_kernel(const float* __restrict__ feat) {
    int base = (blockIdx.x * 256 + threadIdx.x) * 4;
    float4 v = *(const float4*)(feat + base);
    __nv_bfloat162 h0 = __floats2bfloat162_rn(v.x, v.y);
    __nv_bfloat162 h1 = __floats2bfloat162_rn(v.z, v.w);
    *(__nv_bfloat162*)(g_featB + base) = h0;
    *(__nv_bfloat162*)(g_featB + base + 2) = h1;
}

// ---------------------------------------------------------------------------
// Kernel 1: fused  (copy memory -> out)  +  (bf16 GEMM score tile)  +
//           (camera-masked sum of exp(score) per sample, partial per block).
// Block: 512 threads (16 warps, 4x4 over [TM=128 rows] x [BN=256 samples]).
__global__ __launch_bounds__(512, 1) void fused_kernel(
    const float* __restrict__ mem,
    const int*   __restrict__ class_cam,
    const int*   __restrict__ cams,
    float*       __restrict__ out_mem)
{
    // smA: [128][40] bf16 (10240 B), smB: [256][40] bf16 (20480 B)
    // scratch (epilogue, reuses same storage): [16 warps][16*20] f32 (20480 B)
    __shared__ __align__(16) char smraw[10240 + 20480];
    __nv_bfloat16* smA = (__nv_bfloat16*)smraw;
    __nv_bfloat16* smB = (__nv_bfloat16*)(smraw + 10240);
    float* scratch = (float*)smraw;

    __shared__ float sumexp_s[BN];
    __shared__ int   cams_s[BN];
    __shared__ int   camt_s[TM];

    const int tid  = threadIdx.x;
    const int warp = tid >> 5, lane = tid & 31;
    const int wm = warp & 3, wn = warp >> 2;
    const size_t jb = (size_t)blockIdx.x * TM;

    if (tid < BN) { cams_s[tid] = cams[tid]; sumexp_s[tid] = 0.0f; }
    if (tid < TM) camt_s[tid] = class_cam[jb + tid];

    wmma::fragment<wmma::accumulator, 16, 16, 16, float> cfr[2][4];
#pragma unroll
    for (int a = 0; a < 2; ++a)
#pragma unroll
        for (int b = 0; b < 4; ++b) wmma::fill_fragment(cfr[a][b], 0.0f);

    __syncthreads();

    for (int k0 = 0; k0 < DN; k0 += KCH) {
        // -- memory tile: 128 rows x 32 f32. Load f32 (coalesced), copy to out
        //    (scalar: out base is only 4B aligned), convert to bf16 smem.
#pragma unroll
        for (int v = 0; v < 8; ++v) {
            int idx = tid + v * 512;
            int row = idx >> 5, col = idx & 31;
            size_t g = (jb + row) * (size_t)DN + k0 + col;
            float x = mem[g];
            out_mem[g] = x;
            smA[row * 40 + col] = __float2bfloat16(x);
        }
        // -- feature tile: 256 rows x 32 bf16, via 8B chunks (smem stride 80B).
#pragma unroll
        for (int v = 0; v < 4; ++v) {
            int idx = tid + v * 512;
            int row = idx >> 3, cc = idx & 7;
            uint2 u = *(const uint2*)(g_featB + (size_t)row * DN + k0 + cc * 4);
            *(uint2*)(smB + row * 40 + cc * 4) = u;
        }
        __syncthreads();

#pragma unroll
        for (int kk = 0; kk < KCH; kk += 16) {
            wmma::fragment<wmma::matrix_a, 16, 16, 16, __nv_bfloat16, wmma::row_major> af[2];
            wmma::fragment<wmma::matrix_b, 16, 16, 16, __nv_bfloat16, wmma::col_major> bf[4];
#pragma unroll
            for (int a = 0; a < 2; ++a)
                wmma::load_matrix_sync(af[a], smA + (wm * 32 + a * 16) * 40 + kk, 40);
#pragma unroll
            for (int b = 0; b < 4; ++b)
                wmma::load_matrix_sync(bf[b], smB + (wn * 64 + b * 16) * 40 + kk, 40);
#pragma unroll
            for (int a = 0; a < 2; ++a)
#pragma unroll
                for (int b = 0; b < 4; ++b)
                    wmma::mma_sync(cfr[a][b], af[a], bf[b], cfr[a][b]);
        }
        __syncthreads();
    }

    // ---- epilogue: masked exp-sum. Each warp spills one 16x16 frag at a time
    //      into its private scratch slice, then reduces per column (sample).
    float* myscr = scratch + warp * 320;
#pragma unroll
    for (int a = 0; a < 2; ++a) {
#pragma unroll
        for (int b = 0; b < 4; ++b) {
            wmma::store_matrix_sync(myscr, cfr[a][b], 20, wmma::mem_row_major);
            __syncwarp();
            int rowbase = wm * 32 + a * 16;
            int colbase = wn * 64 + b * 16;
            int c  = lane & 15;
            int rh = (lane >> 4) << 3;
            int cam_i = cams_s[colbase + c];
            const float* sp = myscr + rh * 20 + c;
            float s = 0.0f;
#pragma unroll
            for (int t = 0; t < 8; ++t) {
                float e = fast_expscore(sp[t * 20]);
                s += (camt_s[rowbase + rh + t] == cam_i) ? e : 0.0f;
            }
            s += __shfl_down_sync(0xffffffffu, s, 16);
            if (lane < 16) atomicAdd(&sumexp_s[colbase + c], s);
            __syncwarp();
        }
    }
    __syncthreads();
    if (tid < BN) g_partial[blockIdx.x * BN + tid] = sumexp_s[tid];
}

// ---------------------------------------------------------------------------
// Kernel 2: pos[i] = dot(features[i], memory[labels[i]]) / TEMP   (full fp32)
__global__ void pos_kernel(const float* __restrict__ feat,
                           const float* __restrict__ mem,
                           const int*   __restrict__ labels)
{
    int i = blockIdx.x;
    int y = labels[i];
    const float* f = feat + (size_t)i * DN;
    const float* m = mem + (size_t)y * DN;
    float s = 0.0f;
    for (int k = threadIdx.x; k < DN; k += 256) s = fmaf(f[k], m[k], s);
#pragma unroll
    for (int o = 16; o; o >>= 1) s += __shfl_down_sync(0xffffffffu, s, o);
    __shared__ float red[8];
    if ((threadIdx.x & 31) == 0) red[threadIdx.x >> 5] = s;
    __syncthreads();
    if (threadIdx.x == 0) {
        float t = 0.0f;
        for (int w = 0; w < 8; ++w) t += red[w];
        g_pos[i] = t * INV_TEMP;
    }
}

// ---------------------------------------------------------------------------
// Kernel 3: reduce partials -> lse, per-camera means -> loss at out[0].
__global__ void loss_kernel(const int* __restrict__ cams, float* __restrict__ out)
{
    int i = threadIdx.x;  // one thread per sample (256)
    float s = 0.0f;
    for (int b2 = 0; b2 < NBLK; ++b2) s += g_partial[b2 * BN + i];
    float term = logf(s) - g_pos[i];
    __shared__ float csum[8];
    __shared__ int   ccnt[8];
    if (i < 8) { csum[i] = 0.0f; ccnt[i] = 0; }
    __syncthreads();
    int c = cams[i];
    atomicAdd(&csum[c], term);
    atomicAdd(&ccnt[c], 1);
    __syncthreads();
    if (i == 0) {
        float loss = 0.0f;
        for (int c2 = 0; c2 < 8; ++c2)
            if (ccnt[c2] > 0) loss += csum[c2] / (float)ccnt[c2];
        out[0] = loss;
    }
}

// ---------------------------------------------------------------------------
// Kernel 4: EMA + renorm, in place on out_mem (which holds the old memory copy).
// Duplicate labels must chain sequentially: block i processes the full chain
// for labels[i] iff i is the first occurrence; other blocks exit.
__global__ void ema_kernel(const float* __restrict__ feat,
                           const int*   __restrict__ labels,
                           float*       __restrict__ out_mem)
{
    __shared__ int   labs[BN];
    __shared__ float red[8];
    __shared__ float nrm_s;
    __shared__ int   isfirst;
    int i = blockIdx.x, t = threadIdx.x;
    labs[t] = labels[t];
    __syncthreads();
    int y = labs[i];
    if (t == 0) {
        int f = 1;
        for (int u = 0; u < i; ++u) if (labs[u] == y) { f = 0; break; }
        isfirst = f;
    }
    __syncthreads();
    if (!isfirst) return;

    float r[8];
    float* row = out_mem + (size_t)y * DN;
#pragma unroll
    for (int u = 0; u < 8; ++u) r[u] = row[t + u * 256];

    for (int s2 = i; s2 < BN; ++s2) {
        if (labs[s2] != y) continue;   // uniform across block
        const float* x = feat + (size_t)s2 * DN;
        float sq = 0.0f;
#pragma unroll
        for (int u = 0; u < 8; ++u) {
            r[u] = fmaf(0.2f, r[u], 0.8f * x[t + u * 256]);
            sq = fmaf(r[u], r[u], sq);
        }
#pragma unroll
        for (int o = 16; o; o >>= 1) sq += __shfl_down_sync(0xffffffffu, sq, o);
        if ((t & 31) == 0) red[t >> 5] = sq;
        __syncthreads();
        if (t == 0) {
            float tot = 0.0f;
            for (int w = 0; w < 8; ++w) tot += red[w];
            nrm_s = sqrtf(tot);
        }
        __syncthreads();
        float nv = nrm_s;
#pragma unroll
        for (int u = 0; u < 8; ++u) r[u] = r[u] / nv;
    }
#pragma unroll
    for (int u = 0; u < 8; ++u) row[t + u * 256] = r[u];
}

// ---------------------------------------------------------------------------
extern "C" void kernel_launch(void* const* d_in, const int* in_sizes, int n_in,
                              void* d_out, int out_size)
{
    const float* feat   = (const float*)d_in[0];   // [256, 2048] f32
    const int*   labels = (const int*)  d_in[1];   // [256]
    const int*   cams   = (const int*)  d_in[2];   // [256]
    const float* mem    = (const float*)d_in[3];   // [65536, 2048] f32
    const int*   ccam   = (const int*)  d_in[4];   // [65536]

    float* out     = (float*)d_out;   // out[0] = loss
    float* out_mem = out + 1;         // out[1..] = new_memory (4B-aligned only)

    prep_kernel<<<(BN * DN) / 1024, 256>>>(feat);
    fused_kernel<<<NBLK, 512>>>(mem, ccam, cams, out_mem);
    pos_kernel<<<BN, 256>>>(feat, mem, labels);
    loss_kernel<<<1, BN>>>(cams, out);
    ema_kernel<<<BN, 256>>>(feat, labels, out_mem);
}

// round 2
// speedup vs baseline: 1.5865x; 1.5865x over previous
#include <cuda_runtime.h>
#include <cuda_bf16.h>
#include <mma.h>

using namespace nvcuda;

#define BN 256      // batch
#define CN 65536    // classes
#define DN 2048     // feature dim
#define TM 128      // memory rows per block
#define KCH 64      // K chunk
#define NIT (DN / KCH)   // 32
#define NBLK (CN / TM)   // 512
#define LDAB 72          // smem row stride in bf16 elems (144B = 16B*9, ldmatrix conflict-free)
#define STAGE_BYTES (TM * LDAB * 2 + BN * LDAB * 2)   // 18432 + 36864 = 55296
#define SMEM_TOTAL (2 * STAGE_BYTES)                  // 110592

// log2(e)/TEMP,  TEMP = 0.07
#define KSCALE 20.6099292786f
#define INV_TEMP (1.0f / 0.07f)

__device__ __align__(16) __nv_bfloat16 g_featB[BN * DN];  // bf16 features
__device__ float g_partial[BN * NBLK];                    // [sample][tile-block] partial sum-exp
__device__ float g_pos[BN];                               // fp32 positive logits
__device__ float g_term[BN];                              // lse - pos per sample

// exp(score), score = dot / TEMP, computed as 2^(dot * KSCALE). Degree-5 poly.
__device__ __forceinline__ float fast_expscore(float v) {
    float y = v * KSCALE;
    float n = rintf(y);
    float f = y - n;
    float p = 1.3333558e-3f;
    p = fmaf(p, f, 9.6181291e-3f);
    p = fmaf(p, f, 5.5504109e-2f);
    p = fmaf(p, f, 2.4022651e-1f);
    p = fmaf(p, f, 6.9314718e-1f);
    p = fmaf(p, f, 1.0f);
    return __int_as_float(__float_as_int(p) + (((int)n) << 23));
}

// ---------------------------------------------------------------------------
// Kernel 0: features fp32 -> bf16 once.
__global__ void prep_kernel(const float* __restrict__ feat) {
    int base = (blockIdx.x * 256 + threadIdx.x) * 4;
    float4 v = *(const float4*)(feat + base);
    __nv_bfloat162 h0 = __floats2bfloat162_rn(v.x, v.y);
    __nv_bfloat162 h1 = __floats2bfloat162_rn(v.z, v.w);
    *(__nv_bfloat162*)(g_featB + base) = h0;
    *(__nv_bfloat162*)(g_featB + base + 2) = h1;
}

// ---------------------------------------------------------------------------
// Kernel 1: fused (copy memory -> out) + (bf16 GEMM score tile) +
//           (camera-masked exp-sum per sample). Software-pipelined:
//           A(memory f32) via register double-buffer, B(features bf16) via
//           cp.async double-buffer. 512 threads, 16 warps in 4x4 layout.
__global__ __launch_bounds__(512, 1) void fused_kernel(
    const float* __restrict__ mem,
    const int*   __restrict__ class_cam,
    const int*   __restrict__ cams,
    float*       __restrict__ out_mem)
{
    extern __shared__ __align__(16) char dynsm[];
    // stage s: A at s*STAGE_BYTES (128 x LDAB bf16), B at +18432 (256 x LDAB bf16)
    __shared__ float sumexp_s[BN];
    __shared__ int   cams_s[BN];
    __shared__ int   camt_s[TM];

    const int tid  = threadIdx.x;
    const int warp = tid >> 5, lane = tid & 31;
    const int wm = warp & 3, wn = warp >> 2;
    const size_t jb = (size_t)blockIdx.x * TM;

    if (tid < BN) { cams_s[tid] = cams[tid]; sumexp_s[tid] = 0.0f; }
    if (tid < TM) camt_s[tid] = class_cam[jb + tid];

    // per-thread addressing for A tile (128 rows x 64 cols f32, float4 chunks)
    const int arow[4] = { (tid + 0*512) >> 4, (tid + 1*512) >> 4,
                          (tid + 2*512) >> 4, (tid + 3*512) >> 4 };
    const int ac4 = tid & 15;
    // B tile (256 rows x 64 cols bf16, 16B chunks)
    const int brow[4] = { (tid + 0*512) >> 3, (tid + 1*512) >> 3,
                          (tid + 2*512) >> 3, (tid + 3*512) >> 3 };
    const int bc16 = tid & 7;

    wmma::fragment<wmma::accumulator, 16, 16, 16, float> cfr[2][4];
#pragma unroll
    for (int a = 0; a < 2; ++a)
#pragma unroll
        for (int b = 0; b < 4; ++b) wmma::fill_fragment(cfr[a][b], 0.0f);

    float4 ar[4];

    auto loadA = [&](int k0) {
#pragma unroll
        for (int v = 0; v < 4; ++v)
            ar[v] = *(const float4*)(mem + (jb + arow[v]) * (size_t)DN + k0 + ac4 * 4);
    };
    auto cpasyncB = [&](int k0, int stg) {
        unsigned bbase = (unsigned)__cvta_generic_to_shared(dynsm + stg * STAGE_BYTES + TM * LDAB * 2);
#pragma unroll
        for (int v = 0; v < 4; ++v) {
            const void* src = g_featB + (size_t)brow[v] * DN + k0 + bc16 * 8;
            unsigned dst = bbase + brow[v] * (LDAB * 2) + bc16 * 16;
            asm volatile("cp.async.cg.shared.global [%0], [%1], 16;\n" :: "r"(dst), "l"(src));
        }
        asm volatile("cp.async.commit_group;\n");
    };
    auto cvtstoreA = [&](int k0, int stg) {
        __nv_bfloat16* smA = (__nv_bfloat16*)(dynsm + stg * STAGE_BYTES);
#pragma unroll
        for (int v = 0; v < 4; ++v) {
            size_t g = (jb + arow[v]) * (size_t)DN + k0 + ac4 * 4;
            out_mem[g + 0] = ar[v].x;
            out_mem[g + 1] = ar[v].y;
            out_mem[g + 2] = ar[v].z;
            out_mem[g + 3] = ar[v].w;
            __nv_bfloat162 h0 = __floats2bfloat162_rn(ar[v].x, ar[v].y);
            __nv_bfloat162 h1 = __floats2bfloat162_rn(ar[v].z, ar[v].w);
            uint2 p = make_uint2(*(unsigned*)&h0, *(unsigned*)&h1);
            *(uint2*)(smA + arow[v] * LDAB + ac4 * 4) = p;
        }
    };
    auto domma = [&](int stg) {
        const __nv_bfloat16* smA = (const __nv_bfloat16*)(dynsm + stg * STAGE_BYTES);
        const __nv_bfloat16* smB = (const __nv_bfloat16*)(dynsm + stg * STAGE_BYTES + TM * LDAB * 2);
#pragma unroll
        for (int kk = 0; kk < KCH; kk += 16) {
            wmma::fragment<wmma::matrix_a, 16, 16, 16, __nv_bfloat16, wmma::row_major> af[2];
            wmma::fragment<wmma::matrix_b, 16, 16, 16, __nv_bfloat16, wmma::col_major> bf[4];
#pragma unroll
            for (int a = 0; a < 2; ++a)
                wmma::load_matrix_sync(af[a], smA + (wm * 32 + a * 16) * LDAB + kk, LDAB);
#pragma unroll
            for (int b = 0; b < 4; ++b)
                wmma::load_matrix_sync(bf[b], smB + (wn * 64 + b * 16) * LDAB + kk, LDAB);
#pragma unroll
            for (int a = 0; a < 2; ++a)
#pragma unroll
                for (int b = 0; b < 4; ++b)
                    wmma::mma_sync(cfr[a][b], af[a], bf[b], cfr[a][b]);
        }
    };

    // prologue: stage 0
    loadA(0);
    cpasyncB(0, 0);
    cvtstoreA(0, 0);
    asm volatile("cp.async.wait_group 0;\n");
    __syncthreads();

    for (int it = 0; it < NIT; ++it) {
        int cur = it & 1, nxt = cur ^ 1;
        if (it + 1 < NIT) {
            loadA((it + 1) * KCH);
            cpasyncB((it + 1) * KCH, nxt);
        }
        domma(cur);
        if (it + 1 < NIT) {
            cvtstoreA((it + 1) * KCH, nxt);
            asm volatile("cp.async.wait_group 0;\n");
        }
        __syncthreads();
    }

    // ---- epilogue: masked exp-sum (scratch reuses pipeline smem).
    float* scratch = (float*)dynsm;
    float* myscr = scratch + warp * 320;
#pragma unroll
    for (int a = 0; a < 2; ++a) {
#pragma unroll
        for (int b = 0; b < 4; ++b) {
            wmma::store_matrix_sync(myscr, cfr[a][b], 20, wmma::mem_row_major);
            __syncwarp();
            int rowbase = wm * 32 + a * 16;
            int colbase = wn * 64 + b * 16;
            int c  = lane & 15;
            int rh = (lane >> 4) << 3;
            int cam_i = cams_s[colbase + c];
            const float* sp = myscr + rh * 20 + c;
            float s = 0.0f;
#pragma unroll
            for (int t = 0; t < 8; ++t) {
                float e = fast_expscore(sp[t * 20]);
                s += (camt_s[rowbase + rh + t] == cam_i) ? e : 0.0f;
            }
            s += __shfl_down_sync(0xffffffffu, s, 16);
            if (lane < 16) atomicAdd(&sumexp_s[colbase + c], s);
            __syncwarp();
        }
    }
    __syncthreads();
    if (tid < BN) g_partial[(size_t)tid * NBLK + blockIdx.x] = sumexp_s[tid];
}

// ---------------------------------------------------------------------------
// Kernel 2: pos[i] = dot(features[i], memory[labels[i]]) / TEMP (full fp32)
__global__ void pos_kernel(const float* __restrict__ feat,
                           const float* __restrict__ mem,
                           const int*   __restrict__ labels)
{
    int i = blockIdx.x;
    int y = labels[i];
    const float* f = feat + (size_t)i * DN;
    const float* m = mem + (size_t)y * DN;
    float s = 0.0f;
    for (int k = threadIdx.x; k < DN; k += 256) s = fmaf(f[k], m[k], s);
#pragma unroll
    for (int o = 16; o; o >>= 1) s += __shfl_down_sync(0xffffffffu, s, o);
    __shared__ float red[8];
    if ((threadIdx.x & 31) == 0) red[threadIdx.x >> 5] = s;
    __syncthreads();
    if (threadIdx.x == 0) {
        float t = 0.0f;
        for (int w = 0; w < 8; ++w) t += red[w];
        g_pos[i] = t * INV_TEMP;
    }
}

// ---------------------------------------------------------------------------
// Kernel 3a: per-sample reduction of partials -> g_term (coalesced, parallel)
__global__ void reduce_kernel() {
    int i = blockIdx.x;       // sample
    float s = 0.0f;
    for (int j = threadIdx.x; j < NBLK; j += 128)
        s += g_partial[(size_t)i * NBLK + j];
#pragma unroll
    for (int o = 16; o; o >>= 1) s += __shfl_down_sync(0xffffffffu, s, o);
    __shared__ float red[4];
    if ((threadIdx.x & 31) == 0) red[threadIdx.x >> 5] = s;
    __syncthreads();
    if (threadIdx.x == 0) {
        float t = red[0] + red[1] + red[2] + red[3];
        g_term[i] = logf(t) - g_pos[i];
    }
}

// Kernel 3b: camera means -> loss at out[0]
__global__ void loss_final(const int* __restrict__ cams, float* __restrict__ out)
{
    int i = threadIdx.x;      // one thread per sample (256)
    __shared__ float csum[8];
    __shared__ int   ccnt[8];
    if (i < 8) { csum[i] = 0.0f; ccnt[i] = 0; }
    __syncthreads();
    float term = g_term[i];
    int c = cams[i];
    atomicAdd(&csum[c], term);
    atomicAdd(&ccnt[c], 1);
    __syncthreads();
    if (i == 0) {
        float loss = 0.0f;
        for (int c2 = 0; c2 < 8; ++c2)
            if (ccnt[c2] > 0) loss += csum[c2] / (float)ccnt[c2];
        out[0] = loss;
    }
}

// ---------------------------------------------------------------------------
// Kernel 4: EMA + renorm in place on out_mem (holds the old memory copy).
// Duplicate labels chain sequentially inside the first-occurrence block.
__global__ void ema_kernel(const float* __restrict__ feat,
                           const int*   __restrict__ labels,
                           float*       __restrict__ out_mem)
{
    __shared__ int   labs[BN];
    __shared__ float red[8];
    __shared__ float nrm_s;
    __shared__ int   isfirst;
    int i = blockIdx.x, t = threadIdx.x;
    labs[t] = labels[t];
    __syncthreads();
    int y = labs[i];
    if (t == 0) {
        int f = 1;
        for (int u = 0; u < i; ++u) if (labs[u] == y) { f = 0; break; }
        isfirst = f;
    }
    __syncthreads();
    if (!isfirst) return;

    float r[8];
    float* row = out_mem + (size_t)y * DN;
#pragma unroll
    for (int u = 0; u < 8; ++u) r[u] = row[t + u * 256];

    for (int s2 = i; s2 < BN; ++s2) {
        if (labs[s2] != y) continue;   // uniform across block
        const float* x = feat + (size_t)s2 * DN;
        float sq = 0.0f;
#pragma unroll
        for (int u = 0; u < 8; ++u) {
            r[u] = fmaf(0.2f, r[u], 0.8f * x[t + u * 256]);
            sq = fmaf(r[u], r[u], sq);
        }
#pragma unroll
        for (int o = 16; o; o >>= 1) sq += __shfl_down_sync(0xffffffffu, sq, o);
        if ((t & 31) == 0) red[t >> 5] = sq;
        __syncthreads();
        if (t == 0) {
            float tot = 0.0f;
            for (int w = 0; w < 8; ++w) tot += red[w];
            nrm_s = sqrtf(tot);
        }
        __syncthreads();
        float nv = nrm_s;
#pragma unroll
        for (int u = 0; u < 8; ++u) r[u] = r[u] / nv;
    }
#pragma unroll
    for (int u = 0; u < 8; ++u) row[t + u * 256] = r[u];
}

// ---------------------------------------------------------------------------
extern "C" void kernel_launch(void* const* d_in, const int* in_sizes, int n_in,
                              void* d_out, int out_size)
{
    const float* feat   = (const float*)d_in[0];   // [256, 2048] f32
    const int*   labels = (const int*)  d_in[1];   // [256]
    const int*   cams   = (const int*)  d_in[2];   // [256]
    const float* mem    = (const float*)d_in[3];   // [65536, 2048] f32
    const int*   ccam   = (const int*)  d_in[4];   // [65536]

    float* out     = (float*)d_out;   // out[0] = loss
    float* out_mem = out + 1;         // out[1..] = new_memory

    cudaFuncSetAttribute(fused_kernel,
                         cudaFuncAttributeMaxDynamicSharedMemorySize, SMEM_TOTAL);

    prep_kernel<<<(BN * DN) / 1024, 256>>>(feat);
    fused_kernel<<<NBLK, 512, SMEM_TOTAL>>>(mem, ccam, cams, out_mem);
    pos_kernel<<<BN, 256>>>(feat, mem, labels);
    reduce_kernel<<<BN, 128>>>();
    loss_final<<<1, BN>>>(cams, out);
    ema_kernel<<<BN, 256>>>(feat, labels, out_mem);
}

// round 4
// speedup vs baseline: 1.7556x; 1.1066x over previous
#include <cuda_runtime.h>
#include <cuda_bf16.h>
#include <mma.h>
#include <cstdint>

using namespace nvcuda;

#define BN 256      // batch (GEMM N)
#define CN 65536    // classes
#define DN 2048     // feature dim (GEMM K)
#define TM 128      // memory rows per block (GEMM M)
#define KCH 64      // K chunk per stage
#define NIT (DN / KCH)   // 32
#define NBLK (CN / TM)   // 512
#define LDAB 72          // smem row stride (144B), ldmatrix conflict-free
#define A_STAGE (TM * LDAB * 2)   // 18432
#define B_STAGE (BN * LDAB * 2)   // 36864
#define DYN_SMEM (2 * A_STAGE + 3 * B_STAGE)  // 147456

#define KSCALE 20.6099292786f   // log2(e)/TEMP, TEMP=0.07
#define INV_TEMP (1.0f / 0.07f)

__device__ __align__(16) __nv_bfloat16 g_featB[BN * DN];
__device__ float g_partial[BN * NBLK];   // [sample][tile-block]
__device__ float g_pos[BN];
__device__ float g_term[BN];
__device__ int   g_ccnt[8];

__device__ __forceinline__ float fast_expscore(float v) {
    float y = v * KSCALE;
    float n = rintf(y);
    float f = y - n;
    float p = 1.3333558e-3f;
    p = fmaf(p, f, 9.6181291e-3f);
    p = fmaf(p, f, 5.5504109e-2f);
    p = fmaf(p, f, 2.4022651e-1f);
    p = fmaf(p, f, 6.9314718e-1f);
    p = fmaf(p, f, 1.0f);
    return __int_as_float(__float_as_int(p) + (((int)n) << 23));
}

#define CP_COMMIT() asm volatile("cp.async.commit_group;")

// ---------------------------------------------------------------------------
__global__ void prep_kernel(const float* __restrict__ feat) {
    int base = (blockIdx.x * 256 + threadIdx.x) * 4;
    float4 v = *(const float4*)(feat + base);
    __nv_bfloat162 h0 = __floats2bfloat162_rn(v.x, v.y);
    __nv_bfloat162 h1 = __floats2bfloat162_rn(v.z, v.w);
    *(__nv_bfloat162*)(g_featB + base) = h0;
    *(__nv_bfloat162*)(g_featB + base + 2) = h1;
}

// camera counts (also serves as launch-order pad so fused is 4th for ncu)
__global__ void ccnt_kernel(const int* __restrict__ cams) {
    __shared__ int c[8];
    if (threadIdx.x < 8) c[threadIdx.x] = 0;
    __syncthreads();
    atomicAdd(&c[cams[threadIdx.x]], 1);
    __syncthreads();
    if (threadIdx.x < 8) g_ccnt[threadIdx.x] = c[threadIdx.x];
}

// ---------------------------------------------------------------------------
// Fused: copy memory tile -> out, bf16 GEMM (wmma), masked exp-sum epilogue.
// 256 threads / 8 warps. Warp grid 2(M) x 4(N); each warp owns 64x64 (16 frags).
// A: register double-buffer (1 iter ahead).  B: 3-stage cp.async (2 ahead).
__global__ __launch_bounds__(256, 1) void fused_kernel(
    const float* __restrict__ mem,
    const int*   __restrict__ class_cam,
    const int*   __restrict__ cams,
    float*       __restrict__ out_mem)
{
    extern __shared__ __align__(16) char dynsm[];
    // [A0][A1][B0][B1][B2]
    __shared__ float sumexp_s[BN];
    __shared__ int   cams_s[BN];
    __shared__ int   camt_s[TM];

    const int tid  = threadIdx.x;
    const int warp = tid >> 5, lane = tid & 31;
    const int wm = warp & 1, wn = warp >> 1;
    const size_t jb = (size_t)blockIdx.x * TM;

    cams_s[tid] = cams[tid];
    sumexp_s[tid] = 0.0f;
    if (tid < TM) camt_s[tid] = class_cam[jb + tid];

    wmma::fragment<wmma::accumulator, 16, 16, 16, float> cfr[4][4];
#pragma unroll
    for (int a = 0; a < 4; ++a)
#pragma unroll
        for (int b = 0; b < 4; ++b) wmma::fill_fragment(cfr[a][b], 0.0f);

    float4 ar[8];   // A tile: 128x64 f32 = 2048 float4 / 256 thr = 8/thread

    auto loadA = [&](int k0) {
#pragma unroll
        for (int v = 0; v < 8; ++v) {
            int idx = tid + v * 256, row = idx >> 4, c4 = idx & 15;
            ar[v] = *(const float4*)(mem + (jb + row) * (size_t)DN + k0 + c4 * 4);
        }
    };
    auto cvtstoreA = [&](int k0, int stg) {
        __nv_bfloat16* smA = (__nv_bfloat16*)(dynsm + stg * A_STAGE);
#pragma unroll
        for (int v = 0; v < 8; ++v) {
            int idx = tid + v * 256, row = idx >> 4, c4 = idx & 15;
            size_t g = (jb + row) * (size_t)DN + k0 + c4 * 4;
            out_mem[g + 0] = ar[v].x;
            out_mem[g + 1] = ar[v].y;
            out_mem[g + 2] = ar[v].z;
            out_mem[g + 3] = ar[v].w;
            __nv_bfloat162 h0 = __floats2bfloat162_rn(ar[v].x, ar[v].y);
            __nv_bfloat162 h1 = __floats2bfloat162_rn(ar[v].z, ar[v].w);
            *(uint2*)(smA + row * LDAB + c4 * 4) =
                make_uint2(*(uint32_t*)&h0, *(uint32_t*)&h1);
        }
    };
    auto cpasyncB = [&](int k0, int stg) {
        unsigned bbase = (unsigned)__cvta_generic_to_shared(dynsm + 2 * A_STAGE + stg * B_STAGE);
#pragma unroll
        for (int v = 0; v < 8; ++v) {
            int idx = tid + v * 256, row = idx >> 3, c16 = idx & 7;
            const void* src = g_featB + (size_t)row * DN + k0 + c16 * 8;
            unsigned dst = bbase + row * (LDAB * 2) + c16 * 16;
            asm volatile("cp.async.cg.shared.global [%0], [%1], 16;" :: "r"(dst), "l"(src));
        }
        CP_COMMIT();
    };
    auto domma = [&](int stgA, int stgB) {
        const __nv_bfloat16* smA = (const __nv_bfloat16*)(dynsm + stgA * A_STAGE);
        const __nv_bfloat16* smB = (const __nv_bfloat16*)(dynsm + 2 * A_STAGE + stgB * B_STAGE);
#pragma unroll
        for (int kk = 0; kk < KCH; kk += 16) {
            wmma::fragment<wmma::matrix_a, 16, 16, 16, __nv_bfloat16, wmma::row_major> af[4];
            wmma::fragment<wmma::matrix_b, 16, 16, 16, __nv_bfloat16, wmma::col_major> bf[4];
#pragma unroll
            for (int a = 0; a < 4; ++a)
                wmma::load_matrix_sync(af[a], smA + (wm * 64 + a * 16) * LDAB + kk, LDAB);
#pragma unroll
            for (int b = 0; b < 4; ++b)
                wmma::load_matrix_sync(bf[b], smB + (wn * 64 + b * 16) * LDAB + kk, LDAB);
#pragma unroll
            for (int a = 0; a < 4; ++a)
#pragma unroll
                for (int b = 0; b < 4; ++b)
                    wmma::mma_sync(cfr[a][b], af[a], bf[b], cfr[a][b]);
        }
    };

    // prologue
    cpasyncB(0, 0);
    cpasyncB(KCH, 1);
    loadA(0);
    cvtstoreA(0, 0);
    asm volatile("cp.async.wait_group 1;");   // B0 ready, B1 in flight
    __syncthreads();

    for (int it = 0; it < NIT; ++it) {
        if (it + 2 < NIT) cpasyncB((it + 2) * KCH, (it + 2) % 3);
        if (it + 1 < NIT) loadA((it + 1) * KCH);
        domma(it & 1, it % 3);
        if (it + 1 < NIT) {
            cvtstoreA((it + 1) * KCH, (it + 1) & 1);
            if (it + 2 < NIT) asm volatile("cp.async.wait_group 1;");
            else              asm volatile("cp.async.wait_group 0;");
        }
        __syncthreads();
    }

    // ---- epilogue: masked exp-sum (scratch reuses pipeline smem).
    float* scratch = (float*)dynsm;
    float* myscr = scratch + warp * 320;
#pragma unroll
    for (int a = 0; a < 4; ++a) {
#pragma unroll
        for (int b = 0; b < 4; ++b) {
            wmma::store_matrix_sync(myscr, cfr[a][b], 20, wmma::mem_row_major);
            __syncwarp();
            int rowbase = wm * 64 + a * 16;
            int colbase = wn * 64 + b * 16;
            int c  = lane & 15;
            int rh = (lane >> 4) << 3;
            int cam_i = cams_s[colbase + c];
            const float* sp = myscr + rh * 20 + c;
            float s = 0.0f;
#pragma unroll
            for (int t = 0; t < 8; ++t) {
                float e = fast_expscore(sp[t * 20]);
                s += (camt_s[rowbase + rh + t] == cam_i) ? e : 0.0f;
            }
            s += __shfl_down_sync(0xffffffffu, s, 16);
            if (lane < 16) atomicAdd(&sumexp_s[colbase + c], s);
            __syncwarp();
        }
    }
    __syncthreads();
    g_partial[(size_t)tid * NBLK + blockIdx.x] = sumexp_s[tid];
}

// ---------------------------------------------------------------------------
__global__ void pos_kernel(const float* __restrict__ feat,
                           const float* __restrict__ mem,
                           const int*   __restrict__ labels)
{
    int i = blockIdx.x;
    int y = labels[i];
    const float* f = feat + (size_t)i * DN;
    const float* m = mem + (size_t)y * DN;
    float s = 0.0f;
    for (int k = threadIdx.x; k < DN; k += 256) s = fmaf(f[k], m[k], s);
#pragma unroll
    for (int o = 16; o; o >>= 1) s += __shfl_down_sync(0xffffffffu, s, o);
    __shared__ float red[8];
    if ((threadIdx.x & 31) == 0) red[threadIdx.x >> 5] = s;
    __syncthreads();
    if (threadIdx.x == 0) {
        float t = 0.0f;
        for (int w = 0; w < 8; ++w) t += red[w];
        g_pos[i] = t * INV_TEMP;
    }
}

__global__ void reduce_kernel() {
    int i = blockIdx.x;
    float s = 0.0f;
    for (int j = threadIdx.x; j < NBLK; j += 128)
        s += g_partial[(size_t)i * NBLK + j];
#pragma unroll
    for (int o = 16; o; o >>= 1) s += __shfl_down_sync(0xffffffffu, s, o);
    __shared__ float red[4];
    if ((threadIdx.x & 31) == 0) red[threadIdx.x >> 5] = s;
    __syncthreads();
    if (threadIdx.x == 0) {
        float t = red[0] + red[1] + red[2] + red[3];
        g_term[i] = logf(t) - g_pos[i];
    }
}

__global__ void loss_final(const int* __restrict__ cams, float* __restrict__ out)
{
    int i = threadIdx.x;
    __shared__ float csum[8];
    if (i < 8) csum[i] = 0.0f;
    __syncthreads();
    atomicAdd(&csum[cams[i]], g_term[i]);
    __syncthreads();
    if (i == 0) {
        float loss = 0.0f;
        for (int c = 0; c < 8; ++c)
            if (g_ccnt[c] > 0) loss += csum[c] / (float)g_ccnt[c];
        out[0] = loss;
    }
}

// ---------------------------------------------------------------------------
__global__ void ema_kernel(const float* __restrict__ feat,
                           const int*   __restrict__ labels,
                           float*       __restrict__ out_mem)
{
    __shared__ int   labs[BN];
    __shared__ float red[8];
    __shared__ float nrm_s;
    __shared__ int   isfirst;
    int i = blockIdx.x, t = threadIdx.x;
    labs[t] = labels[t];
    __syncthreads();
    int y = labs[i];
    if (t == 0) {
        int f = 1;
        for (int u = 0; u < i; ++u) if (labs[u] == y) { f = 0; break; }
        isfirst = f;
    }
    __syncthreads();
    if (!isfirst) return;

    float r[8];
    float* row = out_mem + (size_t)y * DN;
#pragma unroll
    for (int u = 0; u < 8; ++u) r[u] = row[t + u * 256];

    for (int s2 = i; s2 < BN; ++s2) {
        if (labs[s2] != y) continue;
        const float* x = feat + (size_t)s2 * DN;
        float sq = 0.0f;
#pragma unroll
        for (int u = 0; u < 8; ++u) {
            r[u] = fmaf(0.2f, r[u], 0.8f * x[t + u * 256]);
            sq = fmaf(r[u], r[u], sq);
        }
#pragma unroll
        for (int o = 16; o; o >>= 1) sq += __shfl_down_sync(0xffffffffu, sq, o);
        if ((t & 31) == 0) red[t >> 5] = sq;
        __syncthreads();
        if (t == 0) {
            float tot = 0.0f;
            for (int w = 0; w < 8; ++w) tot += red[w];
            nrm_s = sqrtf(tot);
        }
        __syncthreads();
        float nv = nrm_s;
#pragma unroll
        for (int u = 0; u < 8; ++u) r[u] = r[u] / nv;
    }
#pragma unroll
    for (int u = 0; u < 8; ++u) row[t + u * 256] = r[u];
}

// ---------------------------------------------------------------------------
extern "C" void kernel_launch(void* const* d_in, const int* in_sizes, int n_in,
                              void* d_out, int out_size)
{
    const float* feat   = (const float*)d_in[0];
    const int*   labels = (const int*)  d_in[1];
    const int*   cams   = (const int*)  d_in[2];
    const float* mem    = (const float*)d_in[3];
    const int*   ccam   = (const int*)  d_in[4];

    float* out     = (float*)d_out;
    float* out_mem = out + 1;

    cudaFuncSetAttribute(fused_kernel,
                         cudaFuncAttributeMaxDynamicSharedMemorySize, DYN_SMEM);

    prep_kernel<<<(BN * DN) / 1024, 256>>>(feat);   // 1st
    pos_kernel<<<BN, 256>>>(feat, mem, labels);     // 2nd
    ccnt_kernel<<<1, BN>>>(cams);                   // 3rd (pad so fused is 4th)
    fused_kernel<<<NBLK, 256, DYN_SMEM>>>(mem, ccam, cams, out_mem);  // 4th
    reduce_kernel<<<BN, 128>>>();                   // 5th
    loss_final<<<1, BN>>>(cams, out);               // 6th
    ema_kernel<<<BN, 256>>>(feat, labels, out_mem); // 7th
}